// round 1
// baseline (speedup 1.0000x reference)
#include <cuda_runtime.h>
#include <cstdint>

// Problem constants
#define B    32
#define H    768
#define W    768
#define IMG  (H * W)               // 589824
#define NPIX (B * IMG)             // 18874368
#define RSM_K 35
#define PFM_K 31

// Pass-1 row chunking: 4 chunks of 192 rows (+17 halo each side)
#define CHUNKS 4
#define CHUNK_ROWS (H / CHUNKS)    // 192

// Intermediate: one byte per pixel.
//   bits 0-5 : vertical 35-window popcount (0..35)
//   bit  6   : center mask bit
//   bit  7   : vertical 31-window "any" flag
__device__ uint8_t g_packed[NPIX];

// ---------------------------------------------------------------------------
// Pass 1: vertical sliding bit-window per column.
// grid: B * 3 * CHUNKS blocks of 256 threads (3 x-blocks of 256 cover W=768)
// ---------------------------------------------------------------------------
__global__ __launch_bounds__(256) void pass1_vertical(const float* __restrict__ masks) {
    const int tid   = threadIdx.x;
    const int chunk = blockIdx.x & (CHUNKS - 1);
    int tmp         = blockIdx.x >> 2;          // log2(CHUNKS)=2
    const int xb    = tmp % 3;
    const int b     = tmp / 3;
    const int x     = xb * 256 + tid;

    const int r0 = chunk * CHUNK_ROWS;
    const int r1 = r0 + CHUNK_ROWS;

    const float*  ibase = masks    + (size_t)b * IMG + x;
    uint8_t*      obase = g_packed + (size_t)b * IMG + x;

    const uint64_t M35 = (1ULL << 35) - 1;
    const uint64_t M31 = (1ULL << 31) - 1;

    uint64_t bits = 0;
    #pragma unroll 4
    for (int t = r0 - 17; t < r1 + 17; ++t) {
        uint64_t m = 0;
        if (t >= 0 && t < H) {
            m = (ibase[(size_t)t * W] > 0.5f) ? 1ULL : 0ULL;
        }
        bits = (bits << 1) | m;
        const int y = t - 17;
        if (y >= r0) {
            // bit k of 'bits' = row (t - k)
            uint32_t cnt    = (uint32_t)__popcll(bits & M35);       // rows y-17..y+17
            uint32_t center = (uint32_t)((bits >> 17) & 1ULL);      // row y
            uint32_t flag   = (((bits >> 2) & M31) != 0ULL) ? 1u : 0u; // rows y-15..y+15
            obase[(size_t)y * W] = (uint8_t)(cnt | (center << 6) | (flag << 7));
        }
    }
}

// ---------------------------------------------------------------------------
// Pass 2: per-row horizontal windows via one fused prefix sum.
// grid: B*H blocks of 256 threads; each thread owns 3 contiguous elements for
// the scan, then writes 3 strided (coalesced) outputs.
// ---------------------------------------------------------------------------
__global__ __launch_bounds__(256) void pass2_horizontal(float* __restrict__ out_rsm,
                                                        float* __restrict__ out_pfm) {
    __shared__ uint32_t sPack[W / 4];   // 768 bytes
    __shared__ uint32_t sP[W];          // inclusive prefix: (cnt<<16)|flagcnt
    __shared__ uint32_t sWarp[8];

    const int tid  = threadIdx.x;
    const int lane = tid & 31;
    const int wid  = tid >> 5;
    const int row  = blockIdx.x;        // b*H + y

    const uint8_t* gp = g_packed + (size_t)row * W;
    if (tid < W / 4) sPack[tid] = ((const uint32_t*)gp)[tid];
    __syncthreads();

    const uint8_t* pk = (const uint8_t*)sPack;

    // Per-thread sequential inclusive sums over 3 elements
    const int base_x = 3 * tid;
    uint32_t b0 = pk[base_x + 0];
    uint32_t b1 = pk[base_x + 1];
    uint32_t b2 = pk[base_x + 2];
    uint32_t v0 = ((b0 & 63u) << 16) | (b0 >> 7);
    uint32_t v1 = ((b1 & 63u) << 16) | (b1 >> 7);
    uint32_t v2 = ((b2 & 63u) << 16) | (b2 >> 7);
    uint32_t s0 = v0;
    uint32_t s1 = s0 + v1;
    uint32_t s2 = s1 + v2;

    // Warp inclusive scan of per-thread totals (s2)
    uint32_t sc = s2;
    #pragma unroll
    for (int d = 1; d < 32; d <<= 1) {
        uint32_t y = __shfl_up_sync(0xFFFFFFFFu, sc, d);
        if (lane >= d) sc += y;
    }
    if (lane == 31) sWarp[wid] = sc;
    __syncthreads();
    if (tid < 8) {
        uint32_t w = sWarp[tid];
        #pragma unroll
        for (int d = 1; d < 8; d <<= 1) {
            uint32_t y = __shfl_up_sync(0xFFu, w, d);
            if (tid >= d) w += y;
        }
        sWarp[tid] = w;
    }
    __syncthreads();

    uint32_t excl = (sc - s2) + (wid ? sWarp[wid - 1] : 0u);
    sP[base_x + 0] = excl + s0;
    sP[base_x + 1] = excl + s1;
    sP[base_x + 2] = excl + s2;
    __syncthreads();

    // Outputs: strided so warp writes are coalesced
    float* rsm_row = out_rsm + (size_t)row * W;
    float* pfm_row = out_pfm + (size_t)row * W;

    #pragma unroll
    for (int j = 0; j < 3; ++j) {
        const int x = tid + j * 256;

        const int hi35 = (x + 17 < W - 1) ? x + 17 : W - 1;
        const int lo35 = x - 18;
        uint32_t Phi = sP[hi35];
        uint32_t sum35 = (Phi >> 16) - (lo35 >= 0 ? (sP[lo35] >> 16) : 0u);

        const int hi31 = (x + 15 < W - 1) ? x + 15 : W - 1;
        const int lo31 = x - 16;
        uint32_t Fhi = sP[hi31] & 0xFFFFu;
        uint32_t f31 = Fhi - (lo31 >= 0 ? (sP[lo31] & 0xFFFFu) : 0u);

        rsm_row[x] = (float)sum35 * (1.0f / (float)(RSM_K * RSM_K));

        uint32_t center = (pk[x] >> 6) & 1u;
        float pfm = center ? 1.0f : (f31 ? 0.0f : 2.0f);
        pfm_row[x] = pfm;
    }
}

// ---------------------------------------------------------------------------
extern "C" void kernel_launch(void* const* d_in, const int* in_sizes, int n_in,
                              void* d_out, int out_size) {
    const float* masks = (const float*)d_in[0];
    float* out = (float*)d_out;

    float* out_rsm = out;
    float* out_pfm = out + NPIX;

    // Pass 1: 32 images * 3 x-blocks * 4 row-chunks
    pass1_vertical<<<B * 3 * CHUNKS, 256>>>(masks);
    // Pass 2: one block per (b, y) row
    pass2_horizontal<<<B * H, 256>>>(out_rsm, out_pfm);
}

// round 2
// speedup vs baseline: 1.6289x; 1.6289x over previous
#include <cuda_runtime.h>
#include <cstdint>

// Problem constants
#define B    32
#define H    768
#define W    768
#define IMG  (H * W)               // 589824
#define NPIX (B * IMG)             // 18874368
#define RSM_K 35
#define PFM_K 31

// Pass-1 row chunking: 16 chunks of 48 rows (+17/+16 halo)
#define CHUNKS 16
#define CHUNK_ROWS (H / CHUNKS)    // 48

// Intermediate: one byte per pixel.
//   bits 0-5 : vertical 35-window popcount (0..35)
//   bit  6   : center mask bit
//   bit  7   : vertical 31-window "any" flag
__device__ uint8_t g_packed[NPIX];

// ---------------------------------------------------------------------------
// Pass 1: vertical sliding bit-window per column, explicit load batching for MLP.
// grid: B * 3 * CHUNKS blocks of 256 threads
// ---------------------------------------------------------------------------
__global__ __launch_bounds__(256) void pass1_vertical(const float* __restrict__ masks) {
    const int tid   = threadIdx.x;
    const int chunk = blockIdx.x & (CHUNKS - 1);
    int tmp         = blockIdx.x >> 4;          // log2(CHUNKS)=4
    const int xb    = tmp % 3;
    const int b     = tmp / 3;
    const int x     = xb * 256 + tid;

    const int r0 = chunk * CHUNK_ROWS;

    const float*  ibase = masks    + (size_t)b * IMG + x;
    uint8_t*      obase = g_packed + (size_t)b * IMG + x;

    const uint64_t M35 = (1ULL << 35) - 1;
    const uint64_t M31 = (1ULL << 31) - 1;

    uint64_t bits = 0;

    // Prologue: rows r0-17 .. r0+16 (34 rows). All loads issued before the
    // dependent shift chain -> full MLP.
    {
        uint32_t ml[34];
        #pragma unroll
        for (int i = 0; i < 34; ++i) {
            const int t = r0 - 17 + i;          // t <= 720+16 < H always
            float f = 0.0f;
            if (t >= 0) f = ibase[(size_t)t * W];
            ml[i] = (f > 0.5f) ? 1u : 0u;
        }
        #pragma unroll
        for (int i = 0; i < 34; ++i) bits = (bits << 1) | (uint64_t)ml[i];
    }

    // Emit loop: batches of 8 rows. Loads of the batch are independent of the
    // bits chain -> 8 outstanding LDGs per warp per batch.
    #pragma unroll 1
    for (int yb = 0; yb < CHUNK_ROWS; yb += 8) {
        uint32_t ml[8];
        #pragma unroll
        for (int i = 0; i < 8; ++i) {
            const int t = r0 + yb + i + 17;
            float f = 0.0f;
            if (t < H) f = ibase[(size_t)t * W];
            ml[i] = (f > 0.5f) ? 1u : 0u;
        }
        #pragma unroll
        for (int i = 0; i < 8; ++i) {
            bits = (bits << 1) | (uint64_t)ml[i];
            const int y = r0 + yb + i;
            // bit k of 'bits' = row (current_t - k)
            uint32_t cnt    = (uint32_t)__popcll(bits & M35);          // rows y-17..y+17
            uint32_t center = (uint32_t)((bits >> 17) & 1ULL);         // row y
            uint32_t flag   = (((bits >> 2) & M31) != 0ULL) ? 1u : 0u; // rows y-15..y+15
            obase[(size_t)y * W] = (uint8_t)(cnt | (center << 6) | (flag << 7));
        }
    }
}

// ---------------------------------------------------------------------------
// Pass 2: per-row horizontal windows via one fused prefix sum.
// grid: B*H blocks of 256 threads; each thread owns 3 contiguous elements for
// the scan, then writes 3 strided (coalesced) outputs.
// ---------------------------------------------------------------------------
__global__ __launch_bounds__(256) void pass2_horizontal(float* __restrict__ out_rsm,
                                                        float* __restrict__ out_pfm) {
    __shared__ uint32_t sPack[W / 4];   // 768 bytes
    __shared__ uint32_t sP[W];          // inclusive prefix: (cnt<<16)|flagcnt
    __shared__ uint32_t sWarp[8];

    const int tid  = threadIdx.x;
    const int lane = tid & 31;
    const int wid  = tid >> 5;
    const int row  = blockIdx.x;        // b*H + y

    const uint8_t* gp = g_packed + (size_t)row * W;
    if (tid < W / 4) sPack[tid] = ((const uint32_t*)gp)[tid];
    __syncthreads();

    const uint8_t* pk = (const uint8_t*)sPack;

    // Per-thread sequential inclusive sums over 3 elements
    const int base_x = 3 * tid;
    uint32_t b0 = pk[base_x + 0];
    uint32_t b1 = pk[base_x + 1];
    uint32_t b2 = pk[base_x + 2];
    uint32_t v0 = ((b0 & 63u) << 16) | (b0 >> 7);
    uint32_t v1 = ((b1 & 63u) << 16) | (b1 >> 7);
    uint32_t v2 = ((b2 & 63u) << 16) | (b2 >> 7);
    uint32_t s0 = v0;
    uint32_t s1 = s0 + v1;
    uint32_t s2 = s1 + v2;

    // Warp inclusive scan of per-thread totals (s2)
    uint32_t sc = s2;
    #pragma unroll
    for (int d = 1; d < 32; d <<= 1) {
        uint32_t y = __shfl_up_sync(0xFFFFFFFFu, sc, d);
        if (lane >= d) sc += y;
    }
    if (lane == 31) sWarp[wid] = sc;
    __syncthreads();
    if (tid < 8) {
        uint32_t w = sWarp[tid];
        #pragma unroll
        for (int d = 1; d < 8; d <<= 1) {
            uint32_t y = __shfl_up_sync(0xFFu, w, d);
            if (tid >= d) w += y;
        }
        sWarp[tid] = w;
    }
    __syncthreads();

    uint32_t excl = (sc - s2) + (wid ? sWarp[wid - 1] : 0u);
    sP[base_x + 0] = excl + s0;
    sP[base_x + 1] = excl + s1;
    sP[base_x + 2] = excl + s2;
    __syncthreads();

    // Outputs: strided so warp writes are coalesced
    float* rsm_row = out_rsm + (size_t)row * W;
    float* pfm_row = out_pfm + (size_t)row * W;

    #pragma unroll
    for (int j = 0; j < 3; ++j) {
        const int x = tid + j * 256;

        const int hi35 = (x + 17 < W - 1) ? x + 17 : W - 1;
        const int lo35 = x - 18;
        uint32_t Phi = sP[hi35];
        uint32_t sum35 = (Phi >> 16) - (lo35 >= 0 ? (sP[lo35] >> 16) : 0u);

        const int hi31 = (x + 15 < W - 1) ? x + 15 : W - 1;
        const int lo31 = x - 16;
        uint32_t Fhi = sP[hi31] & 0xFFFFu;
        uint32_t f31 = Fhi - (lo31 >= 0 ? (sP[lo31] & 0xFFFFu) : 0u);

        rsm_row[x] = (float)sum35 * (1.0f / (float)(RSM_K * RSM_K));

        // pfm = center ? 1 : (f31 ? 0 : 2)
        // center=1 implies f31>=1, so this equals center + 2*(f31==0)
        uint32_t center = (pk[x] >> 6) & 1u;
        uint32_t pfm_i = center + ((f31 == 0u) ? 2u : 0u);
        pfm_row[x] = (float)pfm_i;
    }
}

// ---------------------------------------------------------------------------
extern "C" void kernel_launch(void* const* d_in, const int* in_sizes, int n_in,
                              void* d_out, int out_size) {
    const float* masks = (const float*)d_in[0];
    float* out = (float*)d_out;

    float* out_rsm = out;
    float* out_pfm = out + NPIX;

    pass1_vertical<<<B * 3 * CHUNKS, 256>>>(masks);
    pass2_horizontal<<<B * H, 256>>>(out_rsm, out_pfm);
}

// round 3
// speedup vs baseline: 1.8260x; 1.1210x over previous
#include <cuda_runtime.h>
#include <cstdint>

// Problem constants
#define B    32
#define H    768
#define W    768
#define IMG  (H * W)               // 589824
#define NPIX (B * IMG)             // 18874368
#define RSM_K 35
#define PFM_K 31

// Pass-1 row chunking: 12 chunks of 64 rows (+17/+16 halo)
#define CHUNKS 12
#define CHUNK_ROWS (H / CHUNKS)    // 64

// Intermediate: one byte per pixel.
//   bits 0-5 : vertical 35-window popcount (0..35)
//   bit  6   : center mask bit
//   bit  7   : vertical 31-window "any" flag
__device__ uint8_t g_packed[NPIX];

// ---------------------------------------------------------------------------
// Pass 1: vertical sliding bit-window per column, explicit load batching for MLP.
// grid: B * 3 * CHUNKS blocks of 256 threads
// ---------------------------------------------------------------------------
__global__ __launch_bounds__(256) void pass1_vertical(const float* __restrict__ masks) {
    const int tid   = threadIdx.x;
    const int chunk = blockIdx.x % CHUNKS;
    const int tmp   = blockIdx.x / CHUNKS;
    const int xb    = tmp % 3;
    const int b     = tmp / 3;
    const int x     = xb * 256 + tid;

    const int r0 = chunk * CHUNK_ROWS;

    const float*  ibase = masks    + (size_t)b * IMG + x;
    uint8_t*      obase = g_packed + (size_t)b * IMG + x;

    const uint64_t M35 = (1ULL << 35) - 1;
    const uint64_t M31 = (1ULL << 31) - 1;

    uint64_t bits = 0;

    // Prologue: rows r0-17 .. r0+16 (34 rows). All loads issued before the
    // dependent shift chain -> full MLP.
    {
        uint32_t ml[34];
        #pragma unroll
        for (int i = 0; i < 34; ++i) {
            const int t = r0 - 17 + i;          // t < H always here
            float f = 0.0f;
            if (t >= 0) f = ibase[(size_t)t * W];
            ml[i] = (f > 0.5f) ? 1u : 0u;
        }
        #pragma unroll
        for (int i = 0; i < 34; ++i) bits = (bits << 1) | (uint64_t)ml[i];
    }

    // Emit loop: batches of 8 rows; 8 outstanding LDGs per warp per batch.
    #pragma unroll 1
    for (int yb = 0; yb < CHUNK_ROWS; yb += 8) {
        uint32_t ml[8];
        #pragma unroll
        for (int i = 0; i < 8; ++i) {
            const int t = r0 + yb + i + 17;
            float f = 0.0f;
            if (t < H) f = ibase[(size_t)t * W];
            ml[i] = (f > 0.5f) ? 1u : 0u;
        }
        #pragma unroll
        for (int i = 0; i < 8; ++i) {
            bits = (bits << 1) | (uint64_t)ml[i];
            const int y = r0 + yb + i;
            uint32_t cnt    = (uint32_t)__popcll(bits & M35);          // rows y-17..y+17
            uint32_t center = (uint32_t)((bits >> 17) & 1ULL);         // row y
            uint32_t flag   = (((bits >> 2) & M31) != 0ULL) ? 1u : 0u; // rows y-15..y+15
            obase[(size_t)y * W] = (uint8_t)(cnt | (center << 6) | (flag << 7));
        }
    }
}

// ---------------------------------------------------------------------------
// Pass 2: per-row horizontal windows via one fused prefix sum.
// 192 threads per block, one row per block, 4 outputs per thread.
// Prefix array padded: [0..19] zeros, [20..20+W) prefix, [20+W..20+W+16] total.
// ---------------------------------------------------------------------------
#define PAD 20

__global__ __launch_bounds__(192) void pass2_horizontal(float* __restrict__ out_rsm,
                                                        float* __restrict__ out_pfm) {
    __shared__ __align__(16) uint32_t sPp[PAD + W + 17];  // padded fused prefix
    __shared__ uint32_t sWarp[6];

    const int tid  = threadIdx.x;
    const int lane = tid & 31;
    const int wid  = tid >> 5;
    const int row  = blockIdx.x;        // b*H + y
    const int x0   = tid * 4;

    // One u32 = this thread's 4 packed bytes (byte j -> x = x0 + j)
    const uint32_t w = ((const uint32_t*)(g_packed + (size_t)row * W))[tid];

    if (tid < PAD) sPp[tid] = 0;

    // Unpack: v = (cnt << 16) | flag
    uint32_t v0, v1, v2, v3;
    {
        uint32_t c0 = (w      ) & 63u, f0 = (w >> 7 ) & 1u;
        uint32_t c1 = (w >> 8 ) & 63u, f1 = (w >> 15) & 1u;
        uint32_t c2 = (w >> 16) & 63u, f2 = (w >> 23) & 1u;
        uint32_t c3 = (w >> 24) & 63u, f3 = (w >> 31);
        v0 = c0 * 65536u + f0;
        v1 = c1 * 65536u + f1;
        v2 = c2 * 65536u + f2;
        v3 = c3 * 65536u + f3;
    }
    const uint32_t s0 = v0;
    const uint32_t s1 = s0 + v1;
    const uint32_t s2 = s1 + v2;
    const uint32_t s3 = s2 + v3;

    // Warp inclusive scan of per-thread totals
    uint32_t sc = s3;
    #pragma unroll
    for (int d = 1; d < 32; d <<= 1) {
        uint32_t y = __shfl_up_sync(0xFFFFFFFFu, sc, d);
        if (lane >= d) sc += y;
    }
    if (lane == 31) sWarp[wid] = sc;
    __syncthreads();
    if (tid == 0) {
        uint32_t acc = sWarp[0];
        #pragma unroll
        for (int i = 1; i < 6; ++i) { acc += sWarp[i]; sWarp[i] = acc; }
    }
    __syncthreads();

    const uint32_t excl = (sc - s3) + (wid ? sWarp[wid - 1] : 0u);

    // Inclusive prefix at x0..x0+3 (vector STS)
    {
        uint4 p;
        p.x = excl + s0;
        p.y = excl + s1;
        p.z = excl + s2;
        p.w = excl + s3;
        *(uint4*)&sPp[PAD + x0] = p;
    }
    // Right pad: replicate row total P[W-1]
    if (tid < 17) sPp[PAD + W + tid] = sWarp[5];
    __syncthreads();

    // Window reads (all indices pre-shifted by PAD=20):
    //   lo35_j = sPp[x0 + j + 2]   (x - 18 + PAD)
    //   lo31_j = sPp[x0 + j + 4]   (x - 16 + PAD)
    //   hi31_j = sPp[x0 + j + 35]  (x + 15 + PAD, clamp via right pad)
    //   hi35_j = sPp[x0 + j + 37]  (x + 17 + PAD, clamp via right pad)
    const uint2 A01 = *(const uint2*)&sPp[x0 + 2];   // [x0+2, x0+3]
    const uint4 A25 = *(const uint4*)&sPp[x0 + 4];   // [x0+4 .. x0+7]
    const uint32_t b35 = sPp[x0 + 35];
    const uint4 B69 = *(const uint4*)&sPp[x0 + 36];  // [x0+36 .. x0+39]
    const uint32_t b40 = sPp[x0 + 40];

    const float inv = 1.0f / (float)(RSM_K * RSM_K);

    // hi - lo has no cross-field borrow (both fields monotone):
    //   sum35 = (hi35 - lo35) >> 16,  f31 = (hi31 - lo31) & 0xFFFF
    uint32_t d35_0 = B69.y - A01.x;
    uint32_t d35_1 = B69.z - A01.y;
    uint32_t d35_2 = B69.w - A25.x;
    uint32_t d35_3 = b40   - A25.y;

    uint32_t f31_0 = (b35   - A25.x) & 0xFFFFu;
    uint32_t f31_1 = (B69.x - A25.y) & 0xFFFFu;
    uint32_t f31_2 = (B69.y - A25.z) & 0xFFFFu;
    uint32_t f31_3 = (B69.z - A25.w) & 0xFFFFu;

    float4 rsm4;
    rsm4.x = (float)(d35_0 >> 16) * inv;
    rsm4.y = (float)(d35_1 >> 16) * inv;
    rsm4.z = (float)(d35_2 >> 16) * inv;
    rsm4.w = (float)(d35_3 >> 16) * inv;

    // pfm = center ? 1 : (f31 ? 0 : 2) == center + 2*(f31==0)
    float4 pfm4;
    pfm4.x = (float)(((w >> 6)  & 1u) + ((f31_0 == 0u) ? 2u : 0u));
    pfm4.y = (float)(((w >> 14) & 1u) + ((f31_1 == 0u) ? 2u : 0u));
    pfm4.z = (float)(((w >> 22) & 1u) + ((f31_2 == 0u) ? 2u : 0u));
    pfm4.w = (float)(((w >> 30) & 1u) + ((f31_3 == 0u) ? 2u : 0u));

    *(float4*)(out_rsm + (size_t)row * W + x0) = rsm4;
    *(float4*)(out_pfm + (size_t)row * W + x0) = pfm4;
}

// ---------------------------------------------------------------------------
extern "C" void kernel_launch(void* const* d_in, const int* in_sizes, int n_in,
                              void* d_out, int out_size) {
    const float* masks = (const float*)d_in[0];
    float* out = (float*)d_out;

    float* out_rsm = out;
    float* out_pfm = out + NPIX;

    pass1_vertical<<<B * 3 * CHUNKS, 256>>>(masks);
    pass2_horizontal<<<B * H, 192>>>(out_rsm, out_pfm);
}